// round 2
// baseline (speedup 1.0000x reference)
#include <cuda_runtime.h>

// VQC_Registers_BS_density: 16 beam-splitter layers collapse analytically.
//
// State index s = 32*a + b. Even layers rotate a-pairs (2k,2k+1), odd layers
// rotate b-pairs (2m,2m+1); all blocks are R(theta - pi/2) rotations, same-pair
// rotations compose additively, and the 8 * pi/2 offsets cancel (4*pi). So the
// whole circuit is U = R_a(sum theta_even) (x) R_b(sum theta_odd), and
// rho' = U rho U^T is four independent pairwise Givens mixes on the tensor
// indices (a1, b1, a2, b2) of rho[32,32,32,32]. Total traffic: 8 MB.
//
// Round-2 layout: one thread owns rows {r, r+1, r+32, r+33} x cols {c, c+1}
// (8 elements, 4x LDG.64). The a2 mix (col c <-> c+32) is done via
// __shfl_xor_sync(16): lane = q | v<<4 where c = 64p + 2q + 32v. This doubles
// the warp count vs round 1 (131072 threads) to hide memory latency.

__global__ __launch_bounds__(256) void vqc_bs_density_kernel(
    const float* __restrict__ rho,
    const float* __restrict__ angles,
    float* __restrict__ out)
{
    const int tid = blockIdx.x * blockDim.x + threadIdx.x;  // 0..131071

    // Composed angles (uniform; broadcast loads).
    float suma = 0.f, sumb = 0.f;
#pragma unroll
    for (int l = 0; l < 16; l += 2) suma += __ldg(&angles[l]);
#pragma unroll
    for (int l = 1; l < 16; l += 2) sumb += __ldg(&angles[l]);
    float ca, sa, cb, sb;
    sincosf(suma, &sa, &ca);
    sincosf(sumb, &sb, &cb);

    // tid bits: [0:4)=q, [4]=v (a2 half), [5:9)=p, [9:13)=m, [13:17)=k
    const int q = tid & 15;
    const int v = (tid >> 4) & 1;
    const int p = (tid >> 5) & 15;
    const int m = (tid >> 9) & 15;
    const int k = tid >> 13;

    const int r0 = (k << 6) + (m << 1);               // base row = 32*(2k) + 2m
    const int c  = (p << 6) + (q << 1) + (v << 5);    // col = 64p + 2q + 32v

    const float* base  = rho + r0 * 1024 + c;
    float*       obase = out + r0 * 1024 + c;

    // x[i1][j1] = float2 at row (r0 + 32*i1 + j1), cols (c, c+1)
    float2 x00 = *reinterpret_cast<const float2*>(base);
    float2 x01 = *reinterpret_cast<const float2*>(base + 1024);
    float2 x10 = *reinterpret_cast<const float2*>(base + 32768);
    float2 x11 = *reinterpret_cast<const float2*>(base + 33792);

    // a1 mix (ca,sa): i1=0 <-> i1=1 (local)
    {
        float2 t0, t1;
        t0.x = ca * x00.x - sa * x10.x;  t1.x = sa * x00.x + ca * x10.x;
        t0.y = ca * x00.y - sa * x10.y;  t1.y = sa * x00.y + ca * x10.y;
        x00 = t0; x10 = t1;
        t0.x = ca * x01.x - sa * x11.x;  t1.x = sa * x01.x + ca * x11.x;
        t0.y = ca * x01.y - sa * x11.y;  t1.y = sa * x01.y + ca * x11.y;
        x01 = t0; x11 = t1;
    }
    // b1 mix (cb,sb): j1=0 <-> j1=1 (local)
    {
        float2 t0, t1;
        t0.x = cb * x00.x - sb * x01.x;  t1.x = sb * x00.x + cb * x01.x;
        t0.y = cb * x00.y - sb * x01.y;  t1.y = sb * x00.y + cb * x01.y;
        x00 = t0; x01 = t1;
        t0.x = cb * x10.x - sb * x11.x;  t1.x = sb * x10.x + cb * x11.x;
        t0.y = cb * x10.y - sb * x11.y;  t1.y = sb * x10.y + cb * x11.y;
        x10 = t0; x11 = t1;
    }
    // b2 mix (cb,sb): within each float2 (j2=0 <-> j2=1, local)
    {
        float t;
        t = cb * x00.x - sb * x00.y;  x00.y = sb * x00.x + cb * x00.y;  x00.x = t;
        t = cb * x01.x - sb * x01.y;  x01.y = sb * x01.x + cb * x01.y;  x01.x = t;
        t = cb * x10.x - sb * x10.y;  x10.y = sb * x10.x + cb * x10.y;  x10.x = t;
        t = cb * x11.x - sb * x11.y;  x11.y = sb * x11.x + cb * x11.y;  x11.x = t;
    }
    // a2 mix (ca,sa): col c <-> c+32 lives in lane^16 (v bit).
    // v=0 holds the "0" side: e' = ca*e - sa*y ; v=1 holds "1": e' = ca*e + sa*y.
    {
        const float sgn_sa = v ? sa : -sa;
        float y;
        y = __shfl_xor_sync(0xffffffffu, x00.x, 16);  x00.x = ca * x00.x + sgn_sa * y;
        y = __shfl_xor_sync(0xffffffffu, x00.y, 16);  x00.y = ca * x00.y + sgn_sa * y;
        y = __shfl_xor_sync(0xffffffffu, x01.x, 16);  x01.x = ca * x01.x + sgn_sa * y;
        y = __shfl_xor_sync(0xffffffffu, x01.y, 16);  x01.y = ca * x01.y + sgn_sa * y;
        y = __shfl_xor_sync(0xffffffffu, x10.x, 16);  x10.x = ca * x10.x + sgn_sa * y;
        y = __shfl_xor_sync(0xffffffffu, x10.y, 16);  x10.y = ca * x10.y + sgn_sa * y;
        y = __shfl_xor_sync(0xffffffffu, x11.x, 16);  x11.x = ca * x11.x + sgn_sa * y;
        y = __shfl_xor_sync(0xffffffffu, x11.y, 16);  x11.y = ca * x11.y + sgn_sa * y;
    }

    *reinterpret_cast<float2*>(obase)         = x00;
    *reinterpret_cast<float2*>(obase + 1024)  = x01;
    *reinterpret_cast<float2*>(obase + 32768) = x10;
    *reinterpret_cast<float2*>(obase + 33792) = x11;
}

extern "C" void kernel_launch(void* const* d_in, const int* in_sizes, int n_in,
                              void* d_out, int out_size)
{
    const float* rho    = (const float*)d_in[0];  // input_state [1024,1024] f32
    const float* angles = (const float*)d_in[1];  // [16] f32
    // d_in[2..4]: cos/sin/id stacks — analytically folded away, never read.
    float* out = (float*)d_out;

    // 131072 threads: one per 4x2 element group; a2 mix via shfl_xor(16).
    vqc_bs_density_kernel<<<512, 256>>>(rho, angles, out);
}

// round 3
// speedup vs baseline: 1.0335x; 1.0335x over previous
#include <cuda_runtime.h>

// VQC_Registers_BS_density — analytic collapse (see prior rounds):
// whole 16-layer circuit = R_a(sum theta_even) (x) R_b(sum theta_odd);
// rho' = U rho U^T = four independent pairwise Givens mixes on the tensor
// indices (a1, b1, a2, b2) of rho[32,32,32,32]. 8 MB total traffic.
//
// Round 3: (1) angle sums + sincos hoisted to a 1-warp prelude kernel
// (removes the serial 16-load + add-chain + 2x sincosf head from all 65536
// threads); (2) float4 loads/stores: thread owns rows {r0,r0+1,r0+32,r0+33}
// x cols {c..c+3}; the a2 (+32 col) mix is shfl_xor(8).

__device__ float4 g_coef;  // (ca, sa, cb, sb)

__global__ void vqc_angles_kernel(const float* __restrict__ angles)
{
    if (threadIdx.x == 0) {
        float suma = 0.f, sumb = 0.f;
#pragma unroll
        for (int l = 0; l < 16; l += 2) suma += angles[l];
#pragma unroll
        for (int l = 1; l < 16; l += 2) sumb += angles[l];
        float ca, sa, cb, sb;
        sincosf(suma, &sa, &ca);
        sincosf(sumb, &sb, &cb);
        g_coef = make_float4(ca, sa, cb, sb);
    }
}

__device__ __forceinline__ void rot(float& a, float& b, float c, float s)
{
    float t = c * a - s * b;
    b = s * a + c * b;
    a = t;
}

__global__ __launch_bounds__(256) void vqc_bs_density_kernel(
    const float* __restrict__ rho,
    float* __restrict__ out)
{
    const int tid = blockIdx.x * blockDim.x + threadIdx.x;  // 0..65535

    const float4 coef = g_coef;            // uniform broadcast load
    const float ca = coef.x, sa = coef.y, cb = coef.z, sb = coef.w;

    // lane bits: [0:3)=u (col 4u in 32-block), [3]=v (a2 half), [4]=w.
    // Warp covers 128 contiguous columns: c = 4u + 32*(lane>>3) + 128*P.
    const int lane = tid & 31;
    const int P    = (tid >> 5) & 7;
    const int m    = (tid >> 8) & 15;
    const int k    = tid >> 12;

    const int c  = ((lane & 7) << 2) + ((lane >> 3) << 5) + (P << 7);
    const int v  = (lane >> 3) & 1;
    const int r0 = (k << 6) + (m << 1);    // 32*(2k) + 2m

    const float* base  = rho + r0 * 1024 + c;
    float*       obase = out + r0 * 1024 + c;

    // Rows: y00=r0 (i1=0,j1=0), y01=r0+1 (j1=1), y10=r0+32 (i1=1), y11=r0+33.
    float4 y00 = *reinterpret_cast<const float4*>(base);
    float4 y01 = *reinterpret_cast<const float4*>(base + 1024);
    float4 y10 = *reinterpret_cast<const float4*>(base + 32768);
    float4 y11 = *reinterpret_cast<const float4*>(base + 33792);

    // a1 mix (ca,sa): rows r0 <-> r0+32 (per j1, per component)
    rot(y00.x, y10.x, ca, sa);  rot(y00.y, y10.y, ca, sa);
    rot(y00.z, y10.z, ca, sa);  rot(y00.w, y10.w, ca, sa);
    rot(y01.x, y11.x, ca, sa);  rot(y01.y, y11.y, ca, sa);
    rot(y01.z, y11.z, ca, sa);  rot(y01.w, y11.w, ca, sa);

    // b1 mix (cb,sb): rows r0 <-> r0+1 (per i1, per component)
    rot(y00.x, y01.x, cb, sb);  rot(y00.y, y01.y, cb, sb);
    rot(y00.z, y01.z, cb, sb);  rot(y00.w, y01.w, cb, sb);
    rot(y10.x, y11.x, cb, sb);  rot(y10.y, y11.y, cb, sb);
    rot(y10.z, y11.z, cb, sb);  rot(y10.w, y11.w, cb, sb);

    // b2 mix (cb,sb): within float4, col pairs (4u,4u+1) and (4u+2,4u+3)
    rot(y00.x, y00.y, cb, sb);  rot(y00.z, y00.w, cb, sb);
    rot(y01.x, y01.y, cb, sb);  rot(y01.z, y01.w, cb, sb);
    rot(y10.x, y10.y, cb, sb);  rot(y10.z, y10.w, cb, sb);
    rot(y11.x, y11.y, cb, sb);  rot(y11.z, y11.w, cb, sb);

    // a2 mix (ca,sa): col c <-> c+32 lives in lane^8.
    // v=0 side: e' = ca*e - sa*partner ; v=1 side: e' = ca*e + sa*partner.
    {
        const float sg = v ? sa : -sa;
        float p;
        p = __shfl_xor_sync(0xffffffffu, y00.x, 8);  y00.x = ca * y00.x + sg * p;
        p = __shfl_xor_sync(0xffffffffu, y00.y, 8);  y00.y = ca * y00.y + sg * p;
        p = __shfl_xor_sync(0xffffffffu, y00.z, 8);  y00.z = ca * y00.z + sg * p;
        p = __shfl_xor_sync(0xffffffffu, y00.w, 8);  y00.w = ca * y00.w + sg * p;
        p = __shfl_xor_sync(0xffffffffu, y01.x, 8);  y01.x = ca * y01.x + sg * p;
        p = __shfl_xor_sync(0xffffffffu, y01.y, 8);  y01.y = ca * y01.y + sg * p;
        p = __shfl_xor_sync(0xffffffffu, y01.z, 8);  y01.z = ca * y01.z + sg * p;
        p = __shfl_xor_sync(0xffffffffu, y01.w, 8);  y01.w = ca * y01.w + sg * p;
        p = __shfl_xor_sync(0xffffffffu, y10.x, 8);  y10.x = ca * y10.x + sg * p;
        p = __shfl_xor_sync(0xffffffffu, y10.y, 8);  y10.y = ca * y10.y + sg * p;
        p = __shfl_xor_sync(0xffffffffu, y10.z, 8);  y10.z = ca * y10.z + sg * p;
        p = __shfl_xor_sync(0xffffffffu, y10.w, 8);  y10.w = ca * y10.w + sg * p;
        p = __shfl_xor_sync(0xffffffffu, y11.x, 8);  y11.x = ca * y11.x + sg * p;
        p = __shfl_xor_sync(0xffffffffu, y11.y, 8);  y11.y = ca * y11.y + sg * p;
        p = __shfl_xor_sync(0xffffffffu, y11.z, 8);  y11.z = ca * y11.z + sg * p;
        p = __shfl_xor_sync(0xffffffffu, y11.w, 8);  y11.w = ca * y11.w + sg * p;
    }

    *reinterpret_cast<float4*>(obase)         = y00;
    *reinterpret_cast<float4*>(obase + 1024)  = y01;
    *reinterpret_cast<float4*>(obase + 32768) = y10;
    *reinterpret_cast<float4*>(obase + 33792) = y11;
}

extern "C" void kernel_launch(void* const* d_in, const int* in_sizes, int n_in,
                              void* d_out, int out_size)
{
    const float* rho    = (const float*)d_in[0];  // input_state [1024,1024] f32
    const float* angles = (const float*)d_in[1];  // [16] f32
    // d_in[2..4]: cos/sin/id stacks — analytically folded away, never read.
    float* out = (float*)d_out;

    vqc_angles_kernel<<<1, 32>>>(angles);
    vqc_bs_density_kernel<<<256, 256>>>(rho, out);
}

// round 4
// speedup vs baseline: 1.0385x; 1.0048x over previous
#include <cuda_runtime.h>

// VQC_Registers_BS_density — analytic collapse (see prior rounds):
// 16-layer circuit = R_a(sum theta_even) (x) R_b(sum theta_odd);
// rho' = U rho U^T = four independent pairwise Givens mixes on the tensor
// indices (a1, b1, a2, b2) of rho[32,32,32,32]. 8 MB total traffic.
//
// Round 4: fixed-overhead attack.
//  * Single wave: 128 blocks x 512 threads (1 block/SM, no wave transition).
//  * Single kernel node (no prelude launch): rho LDG.128s issued FIRST, angle
//    sum + __sincosf (MUFU fast path) computed under their latency.
//  * Angles loaded as 4x float4 instead of 16 scalars.

__device__ __forceinline__ void rot(float& a, float& b, float c, float s)
{
    float t = c * a - s * b;
    b = s * a + c * b;
    a = t;
}

__global__ __launch_bounds__(512) void vqc_bs_density_kernel(
    const float* __restrict__ rho,
    const float* __restrict__ angles,
    float* __restrict__ out)
{
    const int tid = blockIdx.x * 512 + threadIdx.x;  // 0..65535

    // lane bits: [0:3)=u (float4 within 32-col block), [3]=v (a2 half).
    // Warp covers 128 contiguous columns.
    const int lane = tid & 31;
    const int P    = (tid >> 5) & 7;
    const int m    = (tid >> 8) & 15;
    const int k    = tid >> 12;

    const int c  = ((lane & 7) << 2) + ((lane >> 3) << 5) + (P << 7);
    const int v  = (lane >> 3) & 1;
    const int r0 = (k << 6) + (m << 1);    // 32*(2k) + 2m

    const float* base  = rho + r0 * 1024 + c;
    float*       obase = out + r0 * 1024 + c;

    // Issue the data loads FIRST; angle math below overlaps their latency.
    float4 y00 = *reinterpret_cast<const float4*>(base);
    float4 y01 = *reinterpret_cast<const float4*>(base + 1024);
    float4 y10 = *reinterpret_cast<const float4*>(base + 32768);
    float4 y11 = *reinterpret_cast<const float4*>(base + 33792);

    // Composed angles (uniform; 4x LDG.128 broadcast, tree-sum, MUFU sincos).
    const float4* a4 = reinterpret_cast<const float4*>(angles);
    const float4 A0 = __ldg(a4 + 0), A1 = __ldg(a4 + 1);
    const float4 A2 = __ldg(a4 + 2), A3 = __ldg(a4 + 3);
    const float suma = (A0.x + A0.z) + (A1.x + A1.z)
                     + (A2.x + A2.z) + (A3.x + A3.z);
    const float sumb = (A0.y + A0.w) + (A1.y + A1.w)
                     + (A2.y + A2.w) + (A3.y + A3.w);
    float ca, sa, cb, sb;
    __sincosf(suma, &sa, &ca);
    __sincosf(sumb, &sb, &cb);

    // a1 mix (ca,sa): rows r0 <-> r0+32
    rot(y00.x, y10.x, ca, sa);  rot(y00.y, y10.y, ca, sa);
    rot(y00.z, y10.z, ca, sa);  rot(y00.w, y10.w, ca, sa);
    rot(y01.x, y11.x, ca, sa);  rot(y01.y, y11.y, ca, sa);
    rot(y01.z, y11.z, ca, sa);  rot(y01.w, y11.w, ca, sa);

    // b1 mix (cb,sb): rows r0 <-> r0+1
    rot(y00.x, y01.x, cb, sb);  rot(y00.y, y01.y, cb, sb);
    rot(y00.z, y01.z, cb, sb);  rot(y00.w, y01.w, cb, sb);
    rot(y10.x, y11.x, cb, sb);  rot(y10.y, y11.y, cb, sb);
    rot(y10.z, y11.z, cb, sb);  rot(y10.w, y11.w, cb, sb);

    // b2 mix (cb,sb): within float4, col pairs (c,c+1) and (c+2,c+3)
    rot(y00.x, y00.y, cb, sb);  rot(y00.z, y00.w, cb, sb);
    rot(y01.x, y01.y, cb, sb);  rot(y01.z, y01.w, cb, sb);
    rot(y10.x, y10.y, cb, sb);  rot(y10.z, y10.w, cb, sb);
    rot(y11.x, y11.y, cb, sb);  rot(y11.z, y11.w, cb, sb);

    // a2 mix (ca,sa): col c <-> c+32 lives in lane^8.
    // v=0 side: e' = ca*e - sa*partner ; v=1 side: e' = ca*e + sa*partner.
    {
        const float sg = v ? sa : -sa;
        float p;
        p = __shfl_xor_sync(0xffffffffu, y00.x, 8);  y00.x = ca * y00.x + sg * p;
        p = __shfl_xor_sync(0xffffffffu, y00.y, 8);  y00.y = ca * y00.y + sg * p;
        p = __shfl_xor_sync(0xffffffffu, y00.z, 8);  y00.z = ca * y00.z + sg * p;
        p = __shfl_xor_sync(0xffffffffu, y00.w, 8);  y00.w = ca * y00.w + sg * p;
        p = __shfl_xor_sync(0xffffffffu, y01.x, 8);  y01.x = ca * y01.x + sg * p;
        p = __shfl_xor_sync(0xffffffffu, y01.y, 8);  y01.y = ca * y01.y + sg * p;
        p = __shfl_xor_sync(0xffffffffu, y01.z, 8);  y01.z = ca * y01.z + sg * p;
        p = __shfl_xor_sync(0xffffffffu, y01.w, 8);  y01.w = ca * y01.w + sg * p;
        p = __shfl_xor_sync(0xffffffffu, y10.x, 8);  y10.x = ca * y10.x + sg * p;
        p = __shfl_xor_sync(0xffffffffu, y10.y, 8);  y10.y = ca * y10.y + sg * p;
        p = __shfl_xor_sync(0xffffffffu, y10.z, 8);  y10.z = ca * y10.z + sg * p;
        p = __shfl_xor_sync(0xffffffffu, y10.w, 8);  y10.w = ca * y10.w + sg * p;
        p = __shfl_xor_sync(0xffffffffu, y11.x, 8);  y11.x = ca * y11.x + sg * p;
        p = __shfl_xor_sync(0xffffffffu, y11.y, 8);  y11.y = ca * y11.y + sg * p;
        p = __shfl_xor_sync(0xffffffffu, y11.z, 8);  y11.z = ca * y11.z + sg * p;
        p = __shfl_xor_sync(0xffffffffu, y11.w, 8);  y11.w = ca * y11.w + sg * p;
    }

    *reinterpret_cast<float4*>(obase)         = y00;
    *reinterpret_cast<float4*>(obase + 1024)  = y01;
    *reinterpret_cast<float4*>(obase + 32768) = y10;
    *reinterpret_cast<float4*>(obase + 33792) = y11;
}

extern "C" void kernel_launch(void* const* d_in, const int* in_sizes, int n_in,
                              void* d_out, int out_size)
{
    const float* rho    = (const float*)d_in[0];  // input_state [1024,1024] f32
    const float* angles = (const float*)d_in[1];  // [16] f32
    // d_in[2..4]: cos/sin/id stacks — analytically folded away, never read.
    float* out = (float*)d_out;

    // 65536 threads in a single wave: 128 blocks x 512 threads (<=148 SMs).
    vqc_bs_density_kernel<<<128, 512>>>(rho, angles, out);
}